// round 13
// baseline (speedup 1.0000x reference)
#include <cuda_runtime.h>
#include <cuda_fp16.h>
#include <math.h>
#include <stdint.h>

// Problem constants
#define DIMX   2048
#define HEADS  16
#define HD     128
#define BATCH  4
#define SEQ    2048
#define M_TOT  8192
#define N_TOT  8192
#define K_TOT  2048

// Scan chunking
#define NCHUNK 64
#define CLEN   (SEQ / NCHUNK)        // 32
#define NCH    (BATCH * HEADS * HD)  // 8192

// Scratch
__device__ float  g_combined[(size_t)M_TOT * N_TOT];
__device__ float  g_chunkmax[(size_t)NCHUNK * NCH];
__device__ __half g_Ah[(size_t)M_TOT * K_TOT];
__device__ __half g_Bh[(size_t)N_TOT * K_TOT];

// ---------------------------------------------------------------------------
// PTX helpers
// ---------------------------------------------------------------------------
__device__ __forceinline__ uint32_t smem_u32(const void* p) {
    uint32_t a;
    asm("{ .reg .u64 t; cvta.to.shared.u64 t, %1; cvt.u32.u64 %0, t; }" : "=r"(a) : "l"(p));
    return a;
}
__device__ __forceinline__ void cp_async16(uint32_t dst, const void* src) {
    asm volatile("cp.async.cg.shared.global [%0], [%1], 16;\n" :: "r"(dst), "l"(src));
}
__device__ __forceinline__ void cp_commit() { asm volatile("cp.async.commit_group;\n"); }
template <int N> __device__ __forceinline__ void cp_wait() {
    asm volatile("cp.async.wait_group %0;\n" :: "n"(N));
}
__device__ __forceinline__ void ldmat_x4(uint32_t& r0, uint32_t& r1, uint32_t& r2, uint32_t& r3,
                                         uint32_t addr) {
    asm volatile("ldmatrix.sync.aligned.m8n8.x4.shared.b16 {%0,%1,%2,%3}, [%4];"
                 : "=r"(r0), "=r"(r1), "=r"(r2), "=r"(r3) : "r"(addr));
}
__device__ __forceinline__ void mma_f16(float& c0, float& c1, float& c2, float& c3,
                                        uint32_t a0, uint32_t a1, uint32_t a2, uint32_t a3,
                                        uint32_t b0, uint32_t b1) {
    asm volatile(
        "mma.sync.aligned.m16n8k16.row.col.f32.f16.f16.f32 "
        "{%0,%1,%2,%3}, {%4,%5,%6,%7}, {%8,%9}, {%0,%1,%2,%3};\n"
        : "+f"(c0), "+f"(c1), "+f"(c2), "+f"(c3)
        : "r"(a0), "r"(a1), "r"(a2), "r"(a3), "r"(b0), "r"(b1));
}
#define SWZ128(off) ((off) ^ (((off) >> 3) & 0x70))

// ---------------------------------------------------------------------------
// Kernel 0: convert x and W to fp16 (rn)
// ---------------------------------------------------------------------------
__global__ void cvt_kernel(const float4* __restrict__ x, const float4* __restrict__ w) {
    const size_t N8 = (size_t)M_TOT * K_TOT / 8;
    size_t i = (size_t)blockIdx.x * blockDim.x + threadIdx.x;
    if (i < N8) {
        float4 v0 = x[2 * i], v1 = x[2 * i + 1];
        __half2* o = (__half2*)(g_Ah + 8 * i);
        o[0] = __floats2half2_rn(v0.x, v0.y);
        o[1] = __floats2half2_rn(v0.z, v0.w);
        o[2] = __floats2half2_rn(v1.x, v1.y);
        o[3] = __floats2half2_rn(v1.z, v1.w);
    } else if (i < 2 * N8) {
        size_t j = i - N8;
        float4 v0 = w[2 * j], v1 = w[2 * j + 1];
        __half2* o = (__half2*)(g_Bh + 8 * j);
        o[0] = __floats2half2_rn(v0.x, v0.y);
        o[1] = __floats2half2_rn(v0.z, v0.w);
        o[2] = __floats2half2_rn(v1.x, v1.y);
        o[3] = __floats2half2_rn(v1.z, v1.w);
    }
}

// ---------------------------------------------------------------------------
// Kernel 1: FP16 mma.sync GEMM, warp tile 64x64 (4 warps, 128 threads)
// CTA tile 128x128, BK=64 halves, 3-stage cp.async ring, 96KB smem, occ 2
// (unchanged from R12 — measured ~12us faster than the 8-warp variant)
// ---------------------------------------------------------------------------
#define BM 128
#define BN 128
#define BK 64
#define KT (K_TOT / BK)                        // 32
#define STAGES 3
#define A_STAGE_BYTES (BM * BK * 2)            // 16384
#define B_STAGE_BYTES (BN * BK * 2)            // 16384
#define STAGE_BYTES (A_STAGE_BYTES + B_STAGE_BYTES)
#define SMEM_DYN (STAGES * STAGE_BYTES + 1024) // 99328

__global__ __launch_bounds__(128, 2)
void gemm_f16_kernel() {
    extern __shared__ char dynsmem[];

    const int tid  = threadIdx.x;
    const int warp = tid >> 5;
    const int lane = tid & 31;
    const int bm   = blockIdx.y * BM;
    const int bn   = blockIdx.x * BN;

    const uint32_t sbase = (smem_u32(dynsmem) + 1023u) & ~1023u;

    const int wm = (warp >> 1) * 64;
    const int wn = (warp & 1) * 64;

    const int lr   = lane & 7;
    const int gA1  = (lane >> 3) & 1;
    const int gA2  = lane >> 4;
    const int gB1  = lane >> 4;
    const int gB2  = (lane >> 3) & 1;

    uint32_t aRow[4], bRow[4];
    #pragma unroll
    for (int mf = 0; mf < 4; mf++)
        aRow[mf] = (uint32_t)(wm + mf * 16 + gA1 * 8 + lr) * 128u;
    #pragma unroll
    for (int nfp = 0; nfp < 4; nfp++)
        bRow[nfp] = (uint32_t)(wn + nfp * 16 + gB1 * 8 + lr) * 128u;

    const int lrow = tid >> 3;
    const int lch  = tid & 7;
    const uint32_t base_sw = SWZ128((uint32_t)(lrow * 128 + lch * 16));
    const size_t ofsA_base = (size_t)(bm + lrow) * K_TOT + lch * 8;
    const size_t ofsB_base = (size_t)(bn + lrow) * K_TOT + lch * 8;

    float acc[4][8][4];
    #pragma unroll
    for (int i = 0; i < 4; i++)
        #pragma unroll
        for (int j = 0; j < 8; j++)
            #pragma unroll
            for (int v = 0; v < 4; v++) acc[i][j][v] = 0.0f;

    auto load_stage = [&](int buf, int kt) {
        const uint32_t da = sbase + buf * STAGE_BYTES;
        const uint32_t db = da + A_STAGE_BYTES;
        const uint32_t ko = (uint32_t)(kt * BK);
        #pragma unroll
        for (int i = 0; i < 8; i++)
            cp_async16(da + base_sw + i * 2048u, g_Ah + ofsA_base + (size_t)i * 16 * K_TOT + ko);
        #pragma unroll
        for (int i = 0; i < 8; i++)
            cp_async16(db + base_sw + i * 2048u, g_Bh + ofsB_base + (size_t)i * 16 * K_TOT + ko);
        cp_commit();
    };

    load_stage(0, 0);
    load_stage(1, 1);

    int buf = 0;
    #pragma unroll 1
    for (int kt = 0; kt < KT; kt++) {
        if (kt + 1 < KT) cp_wait<1>(); else cp_wait<0>();
        __syncthreads();

        if (kt + 2 < KT) {
            int nb = buf + 2; if (nb >= STAGES) nb -= STAGES;
            load_stage(nb, kt + 2);
        }

        const uint32_t aOff = sbase + buf * STAGE_BYTES;
        const uint32_t bOff = aOff + A_STAGE_BYTES;

        #pragma unroll
        for (int ks = 0; ks < 4; ks++) {
            const int kc = ks * 2;
            uint32_t a[4][4];
            #pragma unroll
            for (int mf = 0; mf < 4; mf++) {
                uint32_t addr = aOff + aRow[mf] + ((uint32_t)((kc + gA2) ^ lr) << 4);
                ldmat_x4(a[mf][0], a[mf][1], a[mf][2], a[mf][3], addr);
            }
            uint32_t b[4][4];
            #pragma unroll
            for (int nfp = 0; nfp < 4; nfp++) {
                uint32_t addr = bOff + bRow[nfp] + ((uint32_t)((kc + gB2) ^ lr) << 4);
                ldmat_x4(b[nfp][0], b[nfp][1], b[nfp][2], b[nfp][3], addr);
            }
            #pragma unroll
            for (int mf = 0; mf < 4; mf++)
                #pragma unroll
                for (int nfp = 0; nfp < 4; nfp++) {
                    mma_f16(acc[mf][2 * nfp][0], acc[mf][2 * nfp][1],
                            acc[mf][2 * nfp][2], acc[mf][2 * nfp][3],
                            a[mf][0], a[mf][1], a[mf][2], a[mf][3],
                            b[nfp][0], b[nfp][1]);
                    mma_f16(acc[mf][2 * nfp + 1][0], acc[mf][2 * nfp + 1][1],
                            acc[mf][2 * nfp + 1][2], acc[mf][2 * nfp + 1][3],
                            a[mf][0], a[mf][1], a[mf][2], a[mf][3],
                            b[nfp][2], b[nfp][3]);
                }
        }
        buf++; if (buf >= STAGES) buf = 0;
    }

    const int grp = lane >> 2, tig = lane & 3;
    #pragma unroll
    for (int mf = 0; mf < 4; mf++) {
        const int row = bm + wm + mf * 16 + grp;
        #pragma unroll
        for (int nf = 0; nf < 8; nf++) {
            const int col = bn + wn + nf * 8 + 2 * tig;
            *(float2*)(g_combined + (size_t)row * N_TOT + col) =
                make_float2(acc[mf][nf][0], acc[mf][nf][1]);
            *(float2*)(g_combined + (size_t)(row + 8) * N_TOT + col) =
                make_float2(acc[mf][nf][2], acc[mf][nf][3]);
        }
    }
}

// ---------------------------------------------------------------------------
// Kernel 2: per-(channel, chunk) max of c over its sequence chunk (NCHUNK=64)
// ---------------------------------------------------------------------------
__global__ void chunkmax_kernel() {
    const int idx = blockIdx.x * blockDim.x + threadIdx.x;
    if (idx >= NCH * NCHUNK) return;
    const int ch    = idx % NCH;      // consecutive threads -> consecutive hd
    const int chunk = idx / NCH;

    const int b    = ch / (HEADS * HD);
    const int rem  = ch % (HEADS * HD);
    const int head = rem / HD;
    const int hd   = rem % HD;

    const float* cptr = g_combined + (size_t)b * SEQ * N_TOT
                        + (size_t)2 * DIMX + (size_t)head * HD + hd;
    float m = -INFINITY;
    const int s0 = chunk * CLEN;
    for (int s = s0; s < s0 + CLEN; s++) {
        m = fmaxf(m, cptr[(size_t)s * N_TOT]);
    }
    g_chunkmax[(size_t)chunk * NCH + ch] = m;
}

// ---------------------------------------------------------------------------
// Kernel 3 (v3): thread = (chunk, b, head-octet, hd). 8 heads per thread ->
// 32B contiguous (sector-perfect) writes, coalesced reads, no smem/sync.
// 65536 threads in 512 blocks of 128.
// ---------------------------------------------------------------------------
__global__ __launch_bounds__(128)
void scan_out3_kernel(const float* __restrict__ alphas,
                      float* __restrict__ out,
                      long long out_size) {
    const int idx   = blockIdx.x * blockDim.x + threadIdx.x;  // < 64*1024
    const int tg    = idx & 1023;          // (b, half, hd)
    const int chunk = idx >> 10;
    const int b     = tg >> 8;
    const int rem   = tg & 255;
    const int half  = rem >> 7;            // head octet: 0 or 1
    const int hd    = rem & 127;
    const int head0 = half * 8;

    const float a1 = alphas[0];
    const float a2 = alphas[1];
    const float a3 = alphas[2];

    // channel columns (within one projection plane)
    int colv[8];
    #pragma unroll
    for (int h = 0; h < 8; h++) colv[h] = (head0 + h) * HD + hd;

    // carry-in: exclusive prefix max over earlier chunks
    float e[8];
    #pragma unroll
    for (int h = 0; h < 8; h++) e[h] = -INFINITY;
    const int chbase = b * (HEADS * HD);
    for (int j = 0; j < chunk; j++) {
        const float* cm = g_chunkmax + (size_t)j * NCH + chbase;
        #pragma unroll
        for (int h = 0; h < 8; h++) e[h] = fmaxf(e[h], cm[colv[h]]);
    }

    const int s0 = chunk * CLEN;
    const float* base = g_combined + (size_t)(b * SEQ + s0) * N_TOT;
    float* outp = out + (size_t)(b * SEQ + s0) * DIMX + hd * HEADS + head0;

    #pragma unroll 1
    for (int s = 0; s < CLEN; s++) {
        const float* row = base + (size_t)s * N_TOT;
        float o[8];
        #pragma unroll
        for (int h = 0; h < 8; h++) {
            const int c = colv[h];
            const float av = row[c];
            const float bv = row[DIMX + c];
            const float cv = row[2 * DIMX + c];
            const float dv = row[3 * DIMX + c];
            e[h] = fmaxf(e[h], cv);
            o[h] = bv * (av + a1 + cv + e[h]) + a2 * dv
                   + av * fmaf(a3, e[h], dv) + cv * e[h];
        }
        float* w = outp + (size_t)s * DIMX;
        *(float4*)(w + 0) = make_float4(o[0], o[1], o[2], o[3]);
        *(float4*)(w + 4) = make_float4(o[4], o[5], o[6], o[7]);
    }

    // state (final chunk): out[state_base + b*2048 + hd*16 + head0 + h]
    if (chunk == NCHUNK - 1) {
        const size_t state_base = (size_t)BATCH * SEQ * DIMX;
        if (out_size >= (long long)(state_base + (size_t)BATCH * HD * HEADS)) {
            float* w = out + state_base + (size_t)b * (HD * HEADS) + hd * HEADS + head0;
            *(float4*)(w + 0) = make_float4(e[0], e[1], e[2], e[3]);
            *(float4*)(w + 4) = make_float4(e[4], e[5], e[6], e[7]);
        }
    }
}

// ---------------------------------------------------------------------------
extern "C" void kernel_launch(void* const* d_in, const int* in_sizes, int n_in,
                              void* d_out, int out_size) {
    const float* x      = (const float*)d_in[0];
    const float* W      = (const float*)d_in[1];
    const float* alphas = (const float*)d_in[2];
    float* out = (float*)d_out;

    cudaFuncSetAttribute(gemm_f16_kernel,
                         cudaFuncAttributeMaxDynamicSharedMemorySize, SMEM_DYN);

    const size_t cvt_total = 2 * ((size_t)M_TOT * K_TOT / 8);
    cvt_kernel<<<(unsigned)((cvt_total + 255) / 256), 256>>>((const float4*)x, (const float4*)W);

    dim3 gemm_grid(N_TOT / BN, M_TOT / BM);   // (64, 64)
    gemm_f16_kernel<<<gemm_grid, 128, SMEM_DYN>>>();

    const int cm_threads = NCH * NCHUNK;      // 524288
    chunkmax_kernel<<<(cm_threads + 255) / 256, 256>>>();

    scan_out3_kernel<<<(NCHUNK * 1024) / 128, 128>>>(alphas, out, (long long)out_size);
}

// round 14
// speedup vs baseline: 1.6755x; 1.6755x over previous
#include <cuda_runtime.h>
#include <cuda_fp16.h>
#include <math.h>
#include <stdint.h>

// Problem constants
#define DIMX   2048
#define HEADS  16
#define HD     128
#define BATCH  4
#define SEQ    2048
#define M_TOT  8192
#define N_TOT  8192
#define K_TOT  2048

// Scan chunking (R11-proven: 262144 threads)
#define NCHUNK 32
#define CLEN   (SEQ / NCHUNK)        // 64
#define NCH    (BATCH * HEADS * HD)  // 8192

// Scratch
__device__ float  g_combined[(size_t)M_TOT * N_TOT];
__device__ float  g_chunkmax[(size_t)NCHUNK * NCH];
__device__ __half g_Ah[(size_t)M_TOT * K_TOT];
__device__ __half g_Bh[(size_t)N_TOT * K_TOT];

// ---------------------------------------------------------------------------
// PTX helpers
// ---------------------------------------------------------------------------
__device__ __forceinline__ uint32_t smem_u32(const void* p) {
    uint32_t a;
    asm("{ .reg .u64 t; cvta.to.shared.u64 t, %1; cvt.u32.u64 %0, t; }" : "=r"(a) : "l"(p));
    return a;
}
__device__ __forceinline__ void cp_async16(uint32_t dst, const void* src) {
    asm volatile("cp.async.cg.shared.global [%0], [%1], 16;\n" :: "r"(dst), "l"(src));
}
__device__ __forceinline__ void cp_commit() { asm volatile("cp.async.commit_group;\n"); }
template <int N> __device__ __forceinline__ void cp_wait() {
    asm volatile("cp.async.wait_group %0;\n" :: "n"(N));
}
__device__ __forceinline__ void ldmat_x4(uint32_t& r0, uint32_t& r1, uint32_t& r2, uint32_t& r3,
                                         uint32_t addr) {
    asm volatile("ldmatrix.sync.aligned.m8n8.x4.shared.b16 {%0,%1,%2,%3}, [%4];"
                 : "=r"(r0), "=r"(r1), "=r"(r2), "=r"(r3) : "r"(addr));
}
__device__ __forceinline__ void mma_f16(float& c0, float& c1, float& c2, float& c3,
                                        uint32_t a0, uint32_t a1, uint32_t a2, uint32_t a3,
                                        uint32_t b0, uint32_t b1) {
    asm volatile(
        "mma.sync.aligned.m16n8k16.row.col.f32.f16.f16.f32 "
        "{%0,%1,%2,%3}, {%4,%5,%6,%7}, {%8,%9}, {%0,%1,%2,%3};\n"
        : "+f"(c0), "+f"(c1), "+f"(c2), "+f"(c3)
        : "r"(a0), "r"(a1), "r"(a2), "r"(a3), "r"(b0), "r"(b1));
}
#define SWZ128(off) ((off) ^ (((off) >> 3) & 0x70))

// ---------------------------------------------------------------------------
// Kernel 0: convert x and W to fp16 (rn)
// ---------------------------------------------------------------------------
__global__ void cvt_kernel(const float4* __restrict__ x, const float4* __restrict__ w) {
    const size_t N8 = (size_t)M_TOT * K_TOT / 8;
    size_t i = (size_t)blockIdx.x * blockDim.x + threadIdx.x;
    if (i < N8) {
        float4 v0 = x[2 * i], v1 = x[2 * i + 1];
        __half2* o = (__half2*)(g_Ah + 8 * i);
        o[0] = __floats2half2_rn(v0.x, v0.y);
        o[1] = __floats2half2_rn(v0.z, v0.w);
        o[2] = __floats2half2_rn(v1.x, v1.y);
        o[3] = __floats2half2_rn(v1.z, v1.w);
    } else if (i < 2 * N8) {
        size_t j = i - N8;
        float4 v0 = w[2 * j], v1 = w[2 * j + 1];
        __half2* o = (__half2*)(g_Bh + 8 * j);
        o[0] = __floats2half2_rn(v0.x, v0.y);
        o[1] = __floats2half2_rn(v0.z, v0.w);
        o[2] = __floats2half2_rn(v1.x, v1.y);
        o[3] = __floats2half2_rn(v1.z, v1.w);
    }
}

// ---------------------------------------------------------------------------
// Kernel 1: FP16 mma.sync GEMM, warp tile 64x64 (4 warps, 128 threads)
// CTA tile 128x128, BK=64 halves, 3-stage cp.async ring, 96KB smem, occ 2
// (R12-measured best GEMM: ~558us)
// ---------------------------------------------------------------------------
#define BM 128
#define BN 128
#define BK 64
#define KT (K_TOT / BK)                        // 32
#define STAGES 3
#define A_STAGE_BYTES (BM * BK * 2)            // 16384
#define B_STAGE_BYTES (BN * BK * 2)            // 16384
#define STAGE_BYTES (A_STAGE_BYTES + B_STAGE_BYTES)
#define SMEM_DYN (STAGES * STAGE_BYTES + 1024) // 99328

__global__ __launch_bounds__(128, 2)
void gemm_f16_kernel() {
    extern __shared__ char dynsmem[];

    const int tid  = threadIdx.x;
    const int warp = tid >> 5;
    const int lane = tid & 31;
    const int bm   = blockIdx.y * BM;
    const int bn   = blockIdx.x * BN;

    const uint32_t sbase = (smem_u32(dynsmem) + 1023u) & ~1023u;

    const int wm = (warp >> 1) * 64;
    const int wn = (warp & 1) * 64;

    const int lr   = lane & 7;
    const int gA1  = (lane >> 3) & 1;
    const int gA2  = lane >> 4;
    const int gB1  = lane >> 4;
    const int gB2  = (lane >> 3) & 1;

    uint32_t aRow[4], bRow[4];
    #pragma unroll
    for (int mf = 0; mf < 4; mf++)
        aRow[mf] = (uint32_t)(wm + mf * 16 + gA1 * 8 + lr) * 128u;
    #pragma unroll
    for (int nfp = 0; nfp < 4; nfp++)
        bRow[nfp] = (uint32_t)(wn + nfp * 16 + gB1 * 8 + lr) * 128u;

    const int lrow = tid >> 3;
    const int lch  = tid & 7;
    const uint32_t base_sw = SWZ128((uint32_t)(lrow * 128 + lch * 16));
    const size_t ofsA_base = (size_t)(bm + lrow) * K_TOT + lch * 8;
    const size_t ofsB_base = (size_t)(bn + lrow) * K_TOT + lch * 8;

    float acc[4][8][4];
    #pragma unroll
    for (int i = 0; i < 4; i++)
        #pragma unroll
        for (int j = 0; j < 8; j++)
            #pragma unroll
            for (int v = 0; v < 4; v++) acc[i][j][v] = 0.0f;

    auto load_stage = [&](int buf, int kt) {
        const uint32_t da = sbase + buf * STAGE_BYTES;
        const uint32_t db = da + A_STAGE_BYTES;
        const uint32_t ko = (uint32_t)(kt * BK);
        #pragma unroll
        for (int i = 0; i < 8; i++)
            cp_async16(da + base_sw + i * 2048u, g_Ah + ofsA_base + (size_t)i * 16 * K_TOT + ko);
        #pragma unroll
        for (int i = 0; i < 8; i++)
            cp_async16(db + base_sw + i * 2048u, g_Bh + ofsB_base + (size_t)i * 16 * K_TOT + ko);
        cp_commit();
    };

    load_stage(0, 0);
    load_stage(1, 1);

    int buf = 0;
    #pragma unroll 1
    for (int kt = 0; kt < KT; kt++) {
        if (kt + 1 < KT) cp_wait<1>(); else cp_wait<0>();
        __syncthreads();

        if (kt + 2 < KT) {
            int nb = buf + 2; if (nb >= STAGES) nb -= STAGES;
            load_stage(nb, kt + 2);
        }

        const uint32_t aOff = sbase + buf * STAGE_BYTES;
        const uint32_t bOff = aOff + A_STAGE_BYTES;

        #pragma unroll
        for (int ks = 0; ks < 4; ks++) {
            const int kc = ks * 2;
            uint32_t a[4][4];
            #pragma unroll
            for (int mf = 0; mf < 4; mf++) {
                uint32_t addr = aOff + aRow[mf] + ((uint32_t)((kc + gA2) ^ lr) << 4);
                ldmat_x4(a[mf][0], a[mf][1], a[mf][2], a[mf][3], addr);
            }
            uint32_t b[4][4];
            #pragma unroll
            for (int nfp = 0; nfp < 4; nfp++) {
                uint32_t addr = bOff + bRow[nfp] + ((uint32_t)((kc + gB2) ^ lr) << 4);
                ldmat_x4(b[nfp][0], b[nfp][1], b[nfp][2], b[nfp][3], addr);
            }
            #pragma unroll
            for (int mf = 0; mf < 4; mf++)
                #pragma unroll
                for (int nfp = 0; nfp < 4; nfp++) {
                    mma_f16(acc[mf][2 * nfp][0], acc[mf][2 * nfp][1],
                            acc[mf][2 * nfp][2], acc[mf][2 * nfp][3],
                            a[mf][0], a[mf][1], a[mf][2], a[mf][3],
                            b[nfp][0], b[nfp][1]);
                    mma_f16(acc[mf][2 * nfp + 1][0], acc[mf][2 * nfp + 1][1],
                            acc[mf][2 * nfp + 1][2], acc[mf][2 * nfp + 1][3],
                            a[mf][0], a[mf][1], a[mf][2], a[mf][3],
                            b[nfp][2], b[nfp][3]);
                }
        }
        buf++; if (buf >= STAGES) buf = 0;
    }

    const int grp = lane >> 2, tig = lane & 3;
    #pragma unroll
    for (int mf = 0; mf < 4; mf++) {
        const int row = bm + wm + mf * 16 + grp;
        #pragma unroll
        for (int nf = 0; nf < 8; nf++) {
            const int col = bn + wn + nf * 8 + 2 * tig;
            *(float2*)(g_combined + (size_t)row * N_TOT + col) =
                make_float2(acc[mf][nf][0], acc[mf][nf][1]);
            *(float2*)(g_combined + (size_t)(row + 8) * N_TOT + col) =
                make_float2(acc[mf][nf][2], acc[mf][nf][3]);
        }
    }
}

// ---------------------------------------------------------------------------
// Kernel 2 (R11-proven): per-(channel, chunk) max of c over its chunk
// ---------------------------------------------------------------------------
__global__ void chunkmax_kernel() {
    const int idx = blockIdx.x * blockDim.x + threadIdx.x;
    if (idx >= NCH * NCHUNK) return;
    const int ch    = idx % NCH;
    const int chunk = idx / NCH;

    const int b    = ch / (HEADS * HD);
    const int rem  = ch % (HEADS * HD);
    const int head = rem / HD;
    const int hd   = rem % HD;

    const float* cptr = g_combined + (size_t)b * SEQ * N_TOT
                        + (size_t)2 * DIMX + (size_t)head * HD + hd;
    float m = -INFINITY;
    const int s0 = chunk * CLEN;
    for (int s = s0; s < s0 + CLEN; s++) {
        m = fmaxf(m, cptr[(size_t)s * N_TOT]);
    }
    g_chunkmax[(size_t)chunk * NCH + ch] = m;
}

// ---------------------------------------------------------------------------
// Kernel 3 (R11-proven): carry-in, running cummax, fused combine,
// transposed store + state. 262144 threads.
// ---------------------------------------------------------------------------
__global__ void scan_out_kernel(const float* __restrict__ alphas,
                                float* __restrict__ out,
                                long long out_size) {
    const int idx = blockIdx.x * blockDim.x + threadIdx.x;
    if (idx >= NCH * NCHUNK) return;
    const int ch    = idx % NCH;
    const int chunk = idx / NCH;

    const int b    = ch / (HEADS * HD);
    const int rem  = ch % (HEADS * HD);
    const int head = rem / HD;
    const int hd   = rem % HD;

    const float a1 = alphas[0];
    const float a2 = alphas[1];
    const float a3 = alphas[2];

    float e = -INFINITY;
    for (int j = 0; j < chunk; j++)
        e = fmaxf(e, g_chunkmax[(size_t)j * NCH + ch]);

    const float* base = g_combined + (size_t)b * SEQ * N_TOT + (size_t)head * HD + hd;
    float* outp = out + (size_t)b * SEQ * DIMX + (size_t)hd * HEADS + head;

    const int s0 = chunk * CLEN;
    for (int s = s0; s < s0 + CLEN; s++) {
        const float* row = base + (size_t)s * N_TOT;
        const float av = row[0];
        const float bv = row[DIMX];
        const float cv = row[2 * DIMX];
        const float dv = row[3 * DIMX];
        e = fmaxf(e, cv);
        const float o = bv * (av + a1 + cv + e) + a2 * dv
                        + av * fmaf(a3, e, dv) + cv * e;
        outp[(size_t)s * DIMX] = o;
    }

    if (chunk == NCHUNK - 1) {
        const size_t state_base = (size_t)BATCH * SEQ * DIMX;
        if (out_size >= (long long)(state_base + (size_t)BATCH * HD * HEADS)) {
            out[state_base + (size_t)b * HD * HEADS + (size_t)hd * HEADS + head] = e;
        }
    }
}

// ---------------------------------------------------------------------------
extern "C" void kernel_launch(void* const* d_in, const int* in_sizes, int n_in,
                              void* d_out, int out_size) {
    const float* x      = (const float*)d_in[0];
    const float* W      = (const float*)d_in[1];
    const float* alphas = (const float*)d_in[2];
    float* out = (float*)d_out;

    cudaFuncSetAttribute(gemm_f16_kernel,
                         cudaFuncAttributeMaxDynamicSharedMemorySize, SMEM_DYN);

    const size_t cvt_total = 2 * ((size_t)M_TOT * K_TOT / 8);
    cvt_kernel<<<(unsigned)((cvt_total + 255) / 256), 256>>>((const float4*)x, (const float4*)W);

    dim3 gemm_grid(N_TOT / BN, M_TOT / BM);   // (64, 64)
    gemm_f16_kernel<<<gemm_grid, 128, SMEM_DYN>>>();

    const int scan_threads = NCH * NCHUNK;    // 262144
    chunkmax_kernel<<<(scan_threads + 255) / 256, 256>>>();
    scan_out_kernel<<<(scan_threads + 255) / 256, 256>>>(alphas, out, (long long)out_size);
}

// round 16
// speedup vs baseline: 1.7211x; 1.0272x over previous
#include <cuda_runtime.h>
#include <cuda_fp16.h>
#include <math.h>
#include <stdint.h>

// Problem constants
#define DIMX   2048
#define HEADS  16
#define HD     128
#define BATCH  4
#define SEQ    2048
#define M_TOT  8192
#define N_TOT  8192
#define K_TOT  2048
#define NCH    (BATCH * HEADS * HD)  // 8192

// Fine scan chunking: 256 chunks of 8 rows -> 262144 scan threads
#define NCHUNK2 256
#define CLEN2   (SEQ / NCHUNK2)      // 8

// Scratch
__device__ float  g_combined[(size_t)M_TOT * N_TOT];
__device__ float  g_chunkmax2[(size_t)NCHUNK2 * NCH];   // 8 MB
__device__ float  g_cprefix[(size_t)NCHUNK2 * NCH];     // 8 MB
__device__ __half g_Ah[(size_t)M_TOT * K_TOT];
__device__ __half g_Bh[(size_t)N_TOT * K_TOT];

// ---------------------------------------------------------------------------
// PTX helpers
// ---------------------------------------------------------------------------
__device__ __forceinline__ uint32_t smem_u32(const void* p) {
    uint32_t a;
    asm("{ .reg .u64 t; cvta.to.shared.u64 t, %1; cvt.u32.u64 %0, t; }" : "=r"(a) : "l"(p));
    return a;
}
__device__ __forceinline__ void cp_async16(uint32_t dst, const void* src) {
    asm volatile("cp.async.cg.shared.global [%0], [%1], 16;\n" :: "r"(dst), "l"(src));
}
__device__ __forceinline__ void cp_commit() { asm volatile("cp.async.commit_group;\n"); }
template <int N> __device__ __forceinline__ void cp_wait() {
    asm volatile("cp.async.wait_group %0;\n" :: "n"(N));
}
__device__ __forceinline__ void ldmat_x4(uint32_t& r0, uint32_t& r1, uint32_t& r2, uint32_t& r3,
                                         uint32_t addr) {
    asm volatile("ldmatrix.sync.aligned.m8n8.x4.shared.b16 {%0,%1,%2,%3}, [%4];"
                 : "=r"(r0), "=r"(r1), "=r"(r2), "=r"(r3) : "r"(addr));
}
__device__ __forceinline__ void mma_f16(float& c0, float& c1, float& c2, float& c3,
                                        uint32_t a0, uint32_t a1, uint32_t a2, uint32_t a3,
                                        uint32_t b0, uint32_t b1) {
    asm volatile(
        "mma.sync.aligned.m16n8k16.row.col.f32.f16.f16.f32 "
        "{%0,%1,%2,%3}, {%4,%5,%6,%7}, {%8,%9}, {%0,%1,%2,%3};\n"
        : "+f"(c0), "+f"(c1), "+f"(c2), "+f"(c3)
        : "r"(a0), "r"(a1), "r"(a2), "r"(a3), "r"(b0), "r"(b1));
}
#define SWZ128(off) ((off) ^ (((off) >> 3) & 0x70))

// ---------------------------------------------------------------------------
// Kernel 0: convert x and W to fp16 (rn)
// ---------------------------------------------------------------------------
__global__ void cvt_kernel(const float4* __restrict__ x, const float4* __restrict__ w) {
    const size_t N8 = (size_t)M_TOT * K_TOT / 8;
    size_t i = (size_t)blockIdx.x * blockDim.x + threadIdx.x;
    if (i < N8) {
        float4 v0 = x[2 * i], v1 = x[2 * i + 1];
        __half2* o = (__half2*)(g_Ah + 8 * i);
        o[0] = __floats2half2_rn(v0.x, v0.y);
        o[1] = __floats2half2_rn(v0.z, v0.w);
        o[2] = __floats2half2_rn(v1.x, v1.y);
        o[3] = __floats2half2_rn(v1.z, v1.w);
    } else if (i < 2 * N8) {
        size_t j = i - N8;
        float4 v0 = w[2 * j], v1 = w[2 * j + 1];
        __half2* o = (__half2*)(g_Bh + 8 * j);
        o[0] = __floats2half2_rn(v0.x, v0.y);
        o[1] = __floats2half2_rn(v0.z, v0.w);
        o[2] = __floats2half2_rn(v1.x, v1.y);
        o[3] = __floats2half2_rn(v1.z, v1.w);
    }
}

// ---------------------------------------------------------------------------
// Kernel 1: FP16 mma.sync GEMM (R14-proven: ~558us), unchanged
// ---------------------------------------------------------------------------
#define BM 128
#define BN 128
#define BK 64
#define KT (K_TOT / BK)
#define STAGES 3
#define A_STAGE_BYTES (BM * BK * 2)
#define B_STAGE_BYTES (BN * BK * 2)
#define STAGE_BYTES (A_STAGE_BYTES + B_STAGE_BYTES)
#define SMEM_DYN (STAGES * STAGE_BYTES + 1024)

__global__ __launch_bounds__(128, 2)
void gemm_f16_kernel() {
    extern __shared__ char dynsmem[];

    const int tid  = threadIdx.x;
    const int warp = tid >> 5;
    const int lane = tid & 31;
    const int bm   = blockIdx.y * BM;
    const int bn   = blockIdx.x * BN;

    const uint32_t sbase = (smem_u32(dynsmem) + 1023u) & ~1023u;

    const int wm = (warp >> 1) * 64;
    const int wn = (warp & 1) * 64;

    const int lr   = lane & 7;
    const int gA1  = (lane >> 3) & 1;
    const int gA2  = lane >> 4;
    const int gB1  = lane >> 4;
    const int gB2  = (lane >> 3) & 1;

    uint32_t aRow[4], bRow[4];
    #pragma unroll
    for (int mf = 0; mf < 4; mf++)
        aRow[mf] = (uint32_t)(wm + mf * 16 + gA1 * 8 + lr) * 128u;
    #pragma unroll
    for (int nfp = 0; nfp < 4; nfp++)
        bRow[nfp] = (uint32_t)(wn + nfp * 16 + gB1 * 8 + lr) * 128u;

    const int lrow = tid >> 3;
    const int lch  = tid & 7;
    const uint32_t base_sw = SWZ128((uint32_t)(lrow * 128 + lch * 16));
    const size_t ofsA_base = (size_t)(bm + lrow) * K_TOT + lch * 8;
    const size_t ofsB_base = (size_t)(bn + lrow) * K_TOT + lch * 8;

    float acc[4][8][4];
    #pragma unroll
    for (int i = 0; i < 4; i++)
        #pragma unroll
        for (int j = 0; j < 8; j++)
            #pragma unroll
            for (int v = 0; v < 4; v++) acc[i][j][v] = 0.0f;

    auto load_stage = [&](int buf, int kt) {
        const uint32_t da = sbase + buf * STAGE_BYTES;
        const uint32_t db = da + A_STAGE_BYTES;
        const uint32_t ko = (uint32_t)(kt * BK);
        #pragma unroll
        for (int i = 0; i < 8; i++)
            cp_async16(da + base_sw + i * 2048u, g_Ah + ofsA_base + (size_t)i * 16 * K_TOT + ko);
        #pragma unroll
        for (int i = 0; i < 8; i++)
            cp_async16(db + base_sw + i * 2048u, g_Bh + ofsB_base + (size_t)i * 16 * K_TOT + ko);
        cp_commit();
    };

    load_stage(0, 0);
    load_stage(1, 1);

    int buf = 0;
    #pragma unroll 1
    for (int kt = 0; kt < KT; kt++) {
        if (kt + 1 < KT) cp_wait<1>(); else cp_wait<0>();
        __syncthreads();

        if (kt + 2 < KT) {
            int nb = buf + 2; if (nb >= STAGES) nb -= STAGES;
            load_stage(nb, kt + 2);
        }

        const uint32_t aOff = sbase + buf * STAGE_BYTES;
        const uint32_t bOff = aOff + A_STAGE_BYTES;

        #pragma unroll
        for (int ks = 0; ks < 4; ks++) {
            const int kc = ks * 2;
            uint32_t a[4][4];
            #pragma unroll
            for (int mf = 0; mf < 4; mf++) {
                uint32_t addr = aOff + aRow[mf] + ((uint32_t)((kc + gA2) ^ lr) << 4);
                ldmat_x4(a[mf][0], a[mf][1], a[mf][2], a[mf][3], addr);
            }
            uint32_t b[4][4];
            #pragma unroll
            for (int nfp = 0; nfp < 4; nfp++) {
                uint32_t addr = bOff + bRow[nfp] + ((uint32_t)((kc + gB2) ^ lr) << 4);
                ldmat_x4(b[nfp][0], b[nfp][1], b[nfp][2], b[nfp][3], addr);
            }
            #pragma unroll
            for (int mf = 0; mf < 4; mf++)
                #pragma unroll
                for (int nfp = 0; nfp < 4; nfp++) {
                    mma_f16(acc[mf][2 * nfp][0], acc[mf][2 * nfp][1],
                            acc[mf][2 * nfp][2], acc[mf][2 * nfp][3],
                            a[mf][0], a[mf][1], a[mf][2], a[mf][3],
                            b[nfp][0], b[nfp][1]);
                    mma_f16(acc[mf][2 * nfp + 1][0], acc[mf][2 * nfp + 1][1],
                            acc[mf][2 * nfp + 1][2], acc[mf][2 * nfp + 1][3],
                            a[mf][0], a[mf][1], a[mf][2], a[mf][3],
                            b[nfp][2], b[nfp][3]);
                }
        }
        buf++; if (buf >= STAGES) buf = 0;
    }

    const int grp = lane >> 2, tig = lane & 3;
    #pragma unroll
    for (int mf = 0; mf < 4; mf++) {
        const int row = bm + wm + mf * 16 + grp;
        #pragma unroll
        for (int nf = 0; nf < 8; nf++) {
            const int col = bn + wn + nf * 8 + 2 * tig;
            *(float2*)(g_combined + (size_t)row * N_TOT + col) =
                make_float2(acc[mf][nf][0], acc[mf][nf][1]);
            *(float2*)(g_combined + (size_t)(row + 8) * N_TOT + col) =
                make_float2(acc[mf][nf][2], acc[mf][nf][3]);
        }
    }
}

// ---------------------------------------------------------------------------
// Kernel 2: fine chunk max (256 chunks of 8 rows) — 2M threads
// ---------------------------------------------------------------------------
__global__ __launch_bounds__(256)
void chunkmax2_kernel() {
    const int idx = blockIdx.x * blockDim.x + threadIdx.x;
    if (idx >= NCH * NCHUNK2) return;
    const int ch    = idx & (NCH - 1);     // consecutive threads -> consecutive hd
    const int chunk = idx >> 13;           // / 8192

    const int b    = ch >> 11;             // / 2048
    const int rem  = ch & 2047;
    const int head = rem >> 7;
    const int hd   = rem & 127;

    const float* cptr = g_combined + (size_t)b * SEQ * N_TOT
                        + (size_t)2 * DIMX + (size_t)head * HD + hd;
    float m = -INFINITY;
    const int s0 = chunk * CLEN2;
    #pragma unroll
    for (int s = 0; s < CLEN2; s++)
        m = fmaxf(m, cptr[(size_t)(s0 + s) * N_TOT]);
    g_chunkmax2[(size_t)chunk * NCH + ch] = m;
}

// ---------------------------------------------------------------------------
// Kernel 2b: exclusive prefix-max along the chunk axis (Hillis-Steele in smem)
// 512 blocks x 256 threads; block handles 16 channels x 256 chunks
// ---------------------------------------------------------------------------
__global__ __launch_bounds__(256)
void prefix_kernel() {
    __shared__ float sm[2][NCHUNK2 * 16];   // 2 x 16KB

    const int ch0 = blockIdx.x * 16;
    const int t   = threadIdx.x;
    const int jb  = t >> 4;                 // 0..15
    const int c   = t & 15;

    #pragma unroll
    for (int k = 0; k < 16; k++) {
        const int j = jb + 16 * k;
        sm[0][j * 16 + c] = g_chunkmax2[(size_t)j * NCH + ch0 + c];
    }
    __syncthreads();

    int p = 0;
    #pragma unroll
    for (int d = 1; d < NCHUNK2; d <<= 1) {
        #pragma unroll
        for (int k = 0; k < 16; k++) {
            const int j = jb + 16 * k;
            float v = sm[p][j * 16 + c];
            if (j >= d) v = fmaxf(v, sm[p][(j - d) * 16 + c]);
            sm[p ^ 1][j * 16 + c] = v;
        }
        p ^= 1;
        __syncthreads();
    }

    #pragma unroll
    for (int k = 0; k < 16; k++) {
        const int j = jb + 16 * k;
        g_cprefix[(size_t)j * NCH + ch0 + c] =
            (j == 0) ? -INFINITY : sm[p][(j - 1) * 16 + c];
    }
}

// ---------------------------------------------------------------------------
// Kernel 3: fine-chunk scan + combine. thread = (chunk, b, head-octet, hd).
// 262144 threads; 32B sector-perfect contiguous stores, coalesced reads.
// ---------------------------------------------------------------------------
__global__ __launch_bounds__(256)
void scan_out4_kernel(const float* __restrict__ alphas,
                      float* __restrict__ out,
                      long long out_size) {
    const int idx   = blockIdx.x * blockDim.x + threadIdx.x;   // < 256*1024
    const int tg    = idx & 1023;
    const int chunk = idx >> 10;
    const int b     = tg >> 8;
    const int rem   = tg & 255;
    const int half  = rem >> 7;
    const int hd    = rem & 127;
    const int head0 = half * 8;

    const float a1 = alphas[0];
    const float a2 = alphas[1];
    const float a3 = alphas[2];

    int colv[8];
    #pragma unroll
    for (int h = 0; h < 8; h++) colv[h] = (head0 + h) * HD + hd;

    // carry-in from the precomputed exclusive prefix
    const float* pf = g_cprefix + (size_t)chunk * NCH + (size_t)b * (HEADS * HD);
    float e[8];
    #pragma unroll
    for (int h = 0; h < 8; h++) e[h] = pf[colv[h]];

    const int s0 = chunk * CLEN2;
    const float* base = g_combined + (size_t)(b * SEQ + s0) * N_TOT;
    float* outp = out + (size_t)(b * SEQ + s0) * DIMX + hd * HEADS + head0;

    #pragma unroll
    for (int s = 0; s < CLEN2; s++) {
        const float* row = base + (size_t)s * N_TOT;
        float o[8];
        #pragma unroll
        for (int h = 0; h < 8; h++) {
            const int c = colv[h];
            const float av = row[c];
            const float bv = row[DIMX + c];
            const float cv = row[2 * DIMX + c];
            const float dv = row[3 * DIMX + c];
            e[h] = fmaxf(e[h], cv);
            o[h] = bv * (av + a1 + cv + e[h]) + a2 * dv
                   + av * fmaf(a3, e[h], dv) + cv * e[h];
        }
        float* w = outp + (size_t)s * DIMX;
        *(float4*)(w + 0) = make_float4(o[0], o[1], o[2], o[3]);
        *(float4*)(w + 4) = make_float4(o[4], o[5], o[6], o[7]);
    }

    // state from the final chunk
    if (chunk == NCHUNK2 - 1) {
        const size_t state_base = (size_t)BATCH * SEQ * DIMX;
        if (out_size >= (long long)(state_base + (size_t)BATCH * HD * HEADS)) {
            float* w = out + state_base + (size_t)b * (HD * HEADS) + hd * HEADS + head0;
            *(float4*)(w + 0) = make_float4(e[0], e[1], e[2], e[3]);
            *(float4*)(w + 4) = make_float4(e[4], e[5], e[6], e[7]);
        }
    }
}

// ---------------------------------------------------------------------------
extern "C" void kernel_launch(void* const* d_in, const int* in_sizes, int n_in,
                              void* d_out, int out_size) {
    const float* x      = (const float*)d_in[0];
    const float* W      = (const float*)d_in[1];
    const float* alphas = (const float*)d_in[2];
    float* out = (float*)d_out;

    cudaFuncSetAttribute(gemm_f16_kernel,
                         cudaFuncAttributeMaxDynamicSharedMemorySize, SMEM_DYN);

    const size_t cvt_total = 2 * ((size_t)M_TOT * K_TOT / 8);
    cvt_kernel<<<(unsigned)((cvt_total + 255) / 256), 256>>>((const float4*)x, (const float4*)W);

    dim3 gemm_grid(N_TOT / BN, M_TOT / BM);   // (64, 64)
    gemm_f16_kernel<<<gemm_grid, 128, SMEM_DYN>>>();

    chunkmax2_kernel<<<(NCH * NCHUNK2) / 256, 256>>>();          // 8192 blocks
    prefix_kernel<<<NCH / 16, 256>>>();                           // 512 blocks
    scan_out4_kernel<<<(NCHUNK2 * 1024) / 256, 256>>>(alphas, out, (long long)out_size);
}

// round 17
// speedup vs baseline: 1.7517x; 1.0178x over previous
#include <cuda_runtime.h>
#include <cuda_fp16.h>
#include <math.h>
#include <stdint.h>

// Problem constants
#define DIMX   2048
#define HEADS  16
#define HD     128
#define BATCH  4
#define SEQ    2048
#define M_TOT  8192
#define N_TOT  8192
#define K_TOT  2048
#define NCH    (BATCH * HEADS * HD)  // 8192

// Fine scan chunking: 256 chunks of 8 rows -> 262144 scan threads
#define NCHUNK2 256
#define CLEN2   (SEQ / NCHUNK2)      // 8

// Scratch (combined projection now fp16: 128 MB)
__device__ __half g_combined[(size_t)M_TOT * N_TOT];
__device__ float  g_chunkmax2[(size_t)NCHUNK2 * NCH];   // 8 MB
__device__ float  g_cprefix[(size_t)NCHUNK2 * NCH];     // 8 MB
__device__ __half g_Ah[(size_t)M_TOT * K_TOT];
__device__ __half g_Bh[(size_t)N_TOT * K_TOT];

// ---------------------------------------------------------------------------
// PTX helpers
// ---------------------------------------------------------------------------
__device__ __forceinline__ uint32_t smem_u32(const void* p) {
    uint32_t a;
    asm("{ .reg .u64 t; cvta.to.shared.u64 t, %1; cvt.u32.u64 %0, t; }" : "=r"(a) : "l"(p));
    return a;
}
__device__ __forceinline__ void cp_async16(uint32_t dst, const void* src) {
    asm volatile("cp.async.cg.shared.global [%0], [%1], 16;\n" :: "r"(dst), "l"(src));
}
__device__ __forceinline__ void cp_commit() { asm volatile("cp.async.commit_group;\n"); }
template <int N> __device__ __forceinline__ void cp_wait() {
    asm volatile("cp.async.wait_group %0;\n" :: "n"(N));
}
__device__ __forceinline__ void ldmat_x4(uint32_t& r0, uint32_t& r1, uint32_t& r2, uint32_t& r3,
                                         uint32_t addr) {
    asm volatile("ldmatrix.sync.aligned.m8n8.x4.shared.b16 {%0,%1,%2,%3}, [%4];"
                 : "=r"(r0), "=r"(r1), "=r"(r2), "=r"(r3) : "r"(addr));
}
__device__ __forceinline__ void mma_f16(float& c0, float& c1, float& c2, float& c3,
                                        uint32_t a0, uint32_t a1, uint32_t a2, uint32_t a3,
                                        uint32_t b0, uint32_t b1) {
    asm volatile(
        "mma.sync.aligned.m16n8k16.row.col.f32.f16.f16.f32 "
        "{%0,%1,%2,%3}, {%4,%5,%6,%7}, {%8,%9}, {%0,%1,%2,%3};\n"
        : "+f"(c0), "+f"(c1), "+f"(c2), "+f"(c3)
        : "r"(a0), "r"(a1), "r"(a2), "r"(a3), "r"(b0), "r"(b1));
}
#define SWZ128(off) ((off) ^ (((off) >> 3) & 0x70))

// ---------------------------------------------------------------------------
// Kernel 0: convert x and W to fp16 (rn)
// ---------------------------------------------------------------------------
__global__ void cvt_kernel(const float4* __restrict__ x, const float4* __restrict__ w) {
    const size_t N8 = (size_t)M_TOT * K_TOT / 8;
    size_t i = (size_t)blockIdx.x * blockDim.x + threadIdx.x;
    if (i < N8) {
        float4 v0 = x[2 * i], v1 = x[2 * i + 1];
        __half2* o = (__half2*)(g_Ah + 8 * i);
        o[0] = __floats2half2_rn(v0.x, v0.y);
        o[1] = __floats2half2_rn(v0.z, v0.w);
        o[2] = __floats2half2_rn(v1.x, v1.y);
        o[3] = __floats2half2_rn(v1.z, v1.w);
    } else if (i < 2 * N8) {
        size_t j = i - N8;
        float4 v0 = w[2 * j], v1 = w[2 * j + 1];
        __half2* o = (__half2*)(g_Bh + 8 * j);
        o[0] = __floats2half2_rn(v0.x, v0.y);
        o[1] = __floats2half2_rn(v0.z, v0.w);
        o[2] = __floats2half2_rn(v1.x, v1.y);
        o[3] = __floats2half2_rn(v1.z, v1.w);
    }
}

// ---------------------------------------------------------------------------
// Kernel 1: FP16 mma.sync GEMM (R14-proven mainloop), fp16 output stores
// ---------------------------------------------------------------------------
#define BM 128
#define BN 128
#define BK 64
#define KT (K_TOT / BK)
#define STAGES 3
#define A_STAGE_BYTES (BM * BK * 2)
#define B_STAGE_BYTES (BN * BK * 2)
#define STAGE_BYTES (A_STAGE_BYTES + B_STAGE_BYTES)
#define SMEM_DYN (STAGES * STAGE_BYTES + 1024)

__global__ __launch_bounds__(128, 2)
void gemm_f16_kernel() {
    extern __shared__ char dynsmem[];

    const int tid  = threadIdx.x;
    const int warp = tid >> 5;
    const int lane = tid & 31;
    const int bm   = blockIdx.y * BM;
    const int bn   = blockIdx.x * BN;

    const uint32_t sbase = (smem_u32(dynsmem) + 1023u) & ~1023u;

    const int wm = (warp >> 1) * 64;
    const int wn = (warp & 1) * 64;

    const int lr   = lane & 7;
    const int gA1  = (lane >> 3) & 1;
    const int gA2  = lane >> 4;
    const int gB1  = lane >> 4;
    const int gB2  = (lane >> 3) & 1;

    uint32_t aRow[4], bRow[4];
    #pragma unroll
    for (int mf = 0; mf < 4; mf++)
        aRow[mf] = (uint32_t)(wm + mf * 16 + gA1 * 8 + lr) * 128u;
    #pragma unroll
    for (int nfp = 0; nfp < 4; nfp++)
        bRow[nfp] = (uint32_t)(wn + nfp * 16 + gB1 * 8 + lr) * 128u;

    const int lrow = tid >> 3;
    const int lch  = tid & 7;
    const uint32_t base_sw = SWZ128((uint32_t)(lrow * 128 + lch * 16));
    const size_t ofsA_base = (size_t)(bm + lrow) * K_TOT + lch * 8;
    const size_t ofsB_base = (size_t)(bn + lrow) * K_TOT + lch * 8;

    float acc[4][8][4];
    #pragma unroll
    for (int i = 0; i < 4; i++)
        #pragma unroll
        for (int j = 0; j < 8; j++)
            #pragma unroll
            for (int v = 0; v < 4; v++) acc[i][j][v] = 0.0f;

    auto load_stage = [&](int buf, int kt) {
        const uint32_t da = sbase + buf * STAGE_BYTES;
        const uint32_t db = da + A_STAGE_BYTES;
        const uint32_t ko = (uint32_t)(kt * BK);
        #pragma unroll
        for (int i = 0; i < 8; i++)
            cp_async16(da + base_sw + i * 2048u, g_Ah + ofsA_base + (size_t)i * 16 * K_TOT + ko);
        #pragma unroll
        for (int i = 0; i < 8; i++)
            cp_async16(db + base_sw + i * 2048u, g_Bh + ofsB_base + (size_t)i * 16 * K_TOT + ko);
        cp_commit();
    };

    load_stage(0, 0);
    load_stage(1, 1);

    int buf = 0;
    #pragma unroll 1
    for (int kt = 0; kt < KT; kt++) {
        if (kt + 1 < KT) cp_wait<1>(); else cp_wait<0>();
        __syncthreads();

        if (kt + 2 < KT) {
            int nb = buf + 2; if (nb >= STAGES) nb -= STAGES;
            load_stage(nb, kt + 2);
        }

        const uint32_t aOff = sbase + buf * STAGE_BYTES;
        const uint32_t bOff = aOff + A_STAGE_BYTES;

        #pragma unroll
        for (int ks = 0; ks < 4; ks++) {
            const int kc = ks * 2;
            uint32_t a[4][4];
            #pragma unroll
            for (int mf = 0; mf < 4; mf++) {
                uint32_t addr = aOff + aRow[mf] + ((uint32_t)((kc + gA2) ^ lr) << 4);
                ldmat_x4(a[mf][0], a[mf][1], a[mf][2], a[mf][3], addr);
            }
            uint32_t b[4][4];
            #pragma unroll
            for (int nfp = 0; nfp < 4; nfp++) {
                uint32_t addr = bOff + bRow[nfp] + ((uint32_t)((kc + gB2) ^ lr) << 4);
                ldmat_x4(b[nfp][0], b[nfp][1], b[nfp][2], b[nfp][3], addr);
            }
            #pragma unroll
            for (int mf = 0; mf < 4; mf++)
                #pragma unroll
                for (int nfp = 0; nfp < 4; nfp++) {
                    mma_f16(acc[mf][2 * nfp][0], acc[mf][2 * nfp][1],
                            acc[mf][2 * nfp][2], acc[mf][2 * nfp][3],
                            a[mf][0], a[mf][1], a[mf][2], a[mf][3],
                            b[nfp][0], b[nfp][1]);
                    mma_f16(acc[mf][2 * nfp + 1][0], acc[mf][2 * nfp + 1][1],
                            acc[mf][2 * nfp + 1][2], acc[mf][2 * nfp + 1][3],
                            a[mf][0], a[mf][1], a[mf][2], a[mf][3],
                            b[nfp][2], b[nfp][3]);
                }
        }
        buf++; if (buf >= STAGES) buf = 0;
    }

    // Epilogue: fp16 stores. c0,c1 -> (row, col..col+1); c2,c3 -> (row+8, ...)
    const int grp = lane >> 2, tig = lane & 3;
    #pragma unroll
    for (int mf = 0; mf < 4; mf++) {
        const int row = bm + wm + mf * 16 + grp;
        #pragma unroll
        for (int nf = 0; nf < 8; nf++) {
            const int col = bn + wn + nf * 8 + 2 * tig;
            *(__half2*)(g_combined + (size_t)row * N_TOT + col) =
                __floats2half2_rn(acc[mf][nf][0], acc[mf][nf][1]);
            *(__half2*)(g_combined + (size_t)(row + 8) * N_TOT + col) =
                __floats2half2_rn(acc[mf][nf][2], acc[mf][nf][3]);
        }
    }
}

// ---------------------------------------------------------------------------
// Kernel 2: fine chunk max (256 chunks of 8 rows) — 2M threads
// ---------------------------------------------------------------------------
__global__ __launch_bounds__(256)
void chunkmax2_kernel() {
    const int idx = blockIdx.x * blockDim.x + threadIdx.x;
    if (idx >= NCH * NCHUNK2) return;
    const int ch    = idx & (NCH - 1);
    const int chunk = idx >> 13;

    const int b    = ch >> 11;
    const int rem  = ch & 2047;
    const int head = rem >> 7;
    const int hd   = rem & 127;

    const __half* cptr = g_combined + (size_t)b * SEQ * N_TOT
                         + (size_t)2 * DIMX + (size_t)head * HD + hd;
    float m = -INFINITY;
    const int s0 = chunk * CLEN2;
    #pragma unroll
    for (int s = 0; s < CLEN2; s++)
        m = fmaxf(m, __half2float(cptr[(size_t)(s0 + s) * N_TOT]));
    g_chunkmax2[(size_t)chunk * NCH + ch] = m;
}

// ---------------------------------------------------------------------------
// Kernel 2b: exclusive prefix-max along chunks (Hillis-Steele in smem)
// ---------------------------------------------------------------------------
__global__ __launch_bounds__(256)
void prefix_kernel() {
    __shared__ float sm[2][NCHUNK2 * 16];

    const int ch0 = blockIdx.x * 16;
    const int t   = threadIdx.x;
    const int jb  = t >> 4;
    const int c   = t & 15;

    #pragma unroll
    for (int k = 0; k < 16; k++) {
        const int j = jb + 16 * k;
        sm[0][j * 16 + c] = g_chunkmax2[(size_t)j * NCH + ch0 + c];
    }
    __syncthreads();

    int p = 0;
    #pragma unroll
    for (int d = 1; d < NCHUNK2; d <<= 1) {
        #pragma unroll
        for (int k = 0; k < 16; k++) {
            const int j = jb + 16 * k;
            float v = sm[p][j * 16 + c];
            if (j >= d) v = fmaxf(v, sm[p][(j - d) * 16 + c]);
            sm[p ^ 1][j * 16 + c] = v;
        }
        p ^= 1;
        __syncthreads();
    }

    #pragma unroll
    for (int k = 0; k < 16; k++) {
        const int j = jb + 16 * k;
        g_cprefix[(size_t)j * NCH + ch0 + c] =
            (j == 0) ? -INFINITY : sm[p][(j - 1) * 16 + c];
    }
}

// ---------------------------------------------------------------------------
// Kernel 3: fine-chunk scan + combine (fp16 reads, sector-perfect writes)
// ---------------------------------------------------------------------------
__global__ __launch_bounds__(256)
void scan_out4_kernel(const float* __restrict__ alphas,
                      float* __restrict__ out,
                      long long out_size) {
    const int idx   = blockIdx.x * blockDim.x + threadIdx.x;
    const int tg    = idx & 1023;
    const int chunk = idx >> 10;
    const int b     = tg >> 8;
    const int rem   = tg & 255;
    const int half  = rem >> 7;
    const int hd    = rem & 127;
    const int head0 = half * 8;

    const float a1 = alphas[0];
    const float a2 = alphas[1];
    const float a3 = alphas[2];

    int colv[8];
    #pragma unroll
    for (int h = 0; h < 8; h++) colv[h] = (head0 + h) * HD + hd;

    const float* pf = g_cprefix + (size_t)chunk * NCH + (size_t)b * (HEADS * HD);
    float e[8];
    #pragma unroll
    for (int h = 0; h < 8; h++) e[h] = pf[colv[h]];

    const int s0 = chunk * CLEN2;
    const __half* base = g_combined + (size_t)(b * SEQ + s0) * N_TOT;
    float* outp = out + (size_t)(b * SEQ + s0) * DIMX + hd * HEADS + head0;

    #pragma unroll
    for (int s = 0; s < CLEN2; s++) {
        const __half* row = base + (size_t)s * N_TOT;
        float o[8];
        #pragma unroll
        for (int h = 0; h < 8; h++) {
            const int c = colv[h];
            const float av = __half2float(row[c]);
            const float bv = __half2float(row[DIMX + c]);
            const float cv = __half2float(row[2 * DIMX + c]);
            const float dv = __half2float(row[3 * DIMX + c]);
            e[h] = fmaxf(e[h], cv);
            o[h] = bv * (av + a1 + cv + e[h]) + a2 * dv
                   + av * fmaf(a3, e[h], dv) + cv * e[h];
        }
        float* w = outp + (size_t)s * DIMX;
        *(float4*)(w + 0) = make_float4(o[0], o[1], o[2], o[3]);
        *(float4*)(w + 4) = make_float4(o[4], o[5], o[6], o[7]);
    }

    if (chunk == NCHUNK2 - 1) {
        const size_t state_base = (size_t)BATCH * SEQ * DIMX;
        if (out_size >= (long long)(state_base + (size_t)BATCH * HD * HEADS)) {
            float* w = out + state_base + (size_t)b * (HD * HEADS) + hd * HEADS + head0;
            *(float4*)(w + 0) = make_float4(e[0], e[1], e[2], e[3]);
            *(float4*)(w + 4) = make_float4(e[4], e[5], e[6], e[7]);
        }
    }
}

// ---------------------------------------------------------------------------
extern "C" void kernel_launch(void* const* d_in, const int* in_sizes, int n_in,
                              void* d_out, int out_size) {
    const float* x      = (const float*)d_in[0];
    const float* W      = (const float*)d_in[1];
    const float* alphas = (const float*)d_in[2];
    float* out = (float*)d_out;

    cudaFuncSetAttribute(gemm_f16_kernel,
                         cudaFuncAttributeMaxDynamicSharedMemorySize, SMEM_DYN);

    const size_t cvt_total = 2 * ((size_t)M_TOT * K_TOT / 8);
    cvt_kernel<<<(unsigned)((cvt_total + 255) / 256), 256>>>((const float4*)x, (const float4*)W);

    dim3 gemm_grid(N_TOT / BN, M_TOT / BM);   // (64, 64)
    gemm_f16_kernel<<<gemm_grid, 128, SMEM_DYN>>>();

    chunkmax2_kernel<<<(NCH * NCHUNK2) / 256, 256>>>();
    prefix_kernel<<<NCH / 16, 256>>>();
    scan_out4_kernel<<<(NCHUNK2 * 1024) / 256, 256>>>(alphas, out, (long long)out_size);
}